// round 15
// baseline (speedup 1.0000x reference)
#include <cuda_runtime.h>
#include <cuda_bf16.h>
#include <cstdint>
#include <cstddef>

#define T_ 512
#define B_ 64
#define HD_ 256
#define STOP_ 30

// single dynamic-smem symbol
extern __shared__ __align__(16) char dyn_smem[];

// ---------------- device scratch ----------------
__device__ float g_xw[(size_t)2 * T_ * B_ * 1024];   // [dir][t][b][4H]
__device__ float g_h[(size_t)2 * T_ * B_ * HD_];     // [dir][t][b][H]
__device__ float g_htag[(size_t)T_ * B_ * 32];
__device__ float g_Wt[512 * 32];
__device__ __nv_bfloat16 g_ahi[(size_t)32768 * 256];
__device__ __nv_bfloat16 g_alo[(size_t)32768 * 256];
__device__ __nv_bfloat16 g_bhi[(size_t)2048 * 256];
__device__ __nv_bfloat16 g_blo[(size_t)2048 * 256];

// ---------------- PTX helpers ----------------
__device__ __forceinline__ uint32_t smem_u32(const void* p) {
    uint32_t a;
    asm("{ .reg .u64 t; cvta.to.shared.u64 t, %1; cvt.u32.u64 %0, t; }" : "=r"(a) : "l"(p));
    return a;
}
#define LDSM_X4(r, addr) \
    asm volatile("ldmatrix.sync.aligned.m8n8.x4.shared.b16 {%0,%1,%2,%3}, [%4];" \
        : "=r"((r)[0]), "=r"((r)[1]), "=r"((r)[2]), "=r"((r)[3]) : "r"(addr))
#define LDSM_X2(r, addr) \
    asm volatile("ldmatrix.sync.aligned.m8n8.x2.shared.b16 {%0,%1}, [%2];" \
        : "=r"((r)[0]), "=r"((r)[1]) : "r"(addr))
__device__ __forceinline__ void mma16816(float* c, const uint32_t* a, const uint32_t* b) {
    asm volatile("mma.sync.aligned.m16n8k16.row.col.f32.bf16.bf16.f32 "
        "{%0,%1,%2,%3}, {%4,%5,%6,%7}, {%8,%9}, {%0,%1,%2,%3};"
        : "+f"(c[0]), "+f"(c[1]), "+f"(c[2]), "+f"(c[3])
        : "r"(a[0]), "r"(a[1]), "r"(a[2]), "r"(a[3]), "r"(b[0]), "r"(b[1]));
}
#define MBAR_INIT(mb, c) asm volatile("mbarrier.init.shared.b64 [%0], %1;" :: "r"(mb), "r"((uint32_t)(c)) : "memory")
__device__ __forceinline__ void mbar_wait_cl(uint32_t mb, uint32_t parity) {
    asm volatile(
        "{\n\t.reg .pred P;\n\t"
        "WL_%=:\n\t"
        "mbarrier.try_wait.parity.acquire.cluster.shared::cta.b64 P, [%0], %1, 0x989680;\n\t"
        "@P bra WD_%=;\n\t"
        "bra WL_%=;\n\t"
        "WD_%=:\n\t}"
        :: "r"(mb), "r"(parity) : "memory");
}
__device__ __forceinline__ uint32_t mapa_rank(uint32_t a, uint32_t r) {
    uint32_t o;
    asm("mapa.shared::cluster.u32 %0, %1, %2;" : "=r"(o) : "r"(a), "r"(r));
    return o;
}
#define STS_CL_V4(addr, v) \
    asm volatile("st.shared::cluster.v4.b32 [%0], {%1,%2,%3,%4};" \
        :: "r"(addr), "r"((v).x), "r"((v).y), "r"((v).z), "r"((v).w) : "memory")

// =========================================================================
// K0: gather emb rows + split-convert A and B to bf16 hi/lo. (unchanged)
// =========================================================================
__global__ __launch_bounds__(256) void k0_conv(
    const int* __restrict__ inp, const float* __restrict__ emb,
    const float* __restrict__ Wih_f, const float* __restrict__ Wih_b)
{
    size_t u = (size_t)blockIdx.x * 256 + threadIdx.x;
    const float* src;
    __nv_bfloat16 *dhi, *dlo;
    size_t off;
    if (u < 2097152) {
        int r = (int)(u >> 6);
        int q = (int)(u & 63);
        int tok = inp[(r & 63) * T_ + (r >> 6)];
        src = emb + (size_t)tok * 256 + q * 4;
        off = (size_t)r * 256 + q * 4;
        dhi = g_ahi; dlo = g_alo;
    } else {
        size_t v = u - 2097152;
        if (v >= 131072) return;
        int r = (int)(v >> 6);
        int q = (int)(v & 63);
        src = (r < 1024 ? Wih_f + (size_t)r * 256
                        : Wih_b + (size_t)(r - 1024) * 256) + q * 4;
        off = (size_t)r * 256 + q * 4;
        dhi = g_bhi; dlo = g_blo;
    }
    float4 a = *(const float4*)src;
    __nv_bfloat162 h0 = __floats2bfloat162_rn(a.x, a.y);
    __nv_bfloat162 h1 = __floats2bfloat162_rn(a.z, a.w);
    __nv_bfloat162 l0 = __floats2bfloat162_rn(a.x - __bfloat162float(h0.x),
                                              a.y - __bfloat162float(h0.y));
    __nv_bfloat162 l1 = __floats2bfloat162_rn(a.z - __bfloat162float(h1.x),
                                              a.w - __bfloat162float(h1.y));
    *(uint2*)(dhi + off) = make_uint2(*(uint32_t*)&h0, *(uint32_t*)&h1);
    *(uint2*)(dlo + off) = make_uint2(*(uint32_t*)&l0, *(uint32_t*)&l1);
}

// =========================================================================
// K1: xW = A @ B^T + bias via mma.sync bf16 split (unchanged).
// =========================================================================
#define K1_STR  72
#define K1_AHI  0
#define K1_ALO  (128 * K1_STR)
#define K1_BHI  (2 * 128 * K1_STR)
#define K1_BLO  (3 * 128 * K1_STR)
#define K1_BIAS_B (4 * 128 * K1_STR * 2)
#define K1_SMEM (K1_BIAS_B + 512 + 128)

__global__ __launch_bounds__(256, 2) void k1_mma(
    const float* __restrict__ b_f, const float* __restrict__ b_b)
{
    __nv_bfloat16* smb = (__nv_bfloat16*)dyn_smem;
    float* sbias = (float*)(dyn_smem + K1_BIAS_B);
    const uint32_t sA = smem_u32(smb);
    const int tid = threadIdx.x;
    const int wid = tid >> 5, lane = tid & 31;
    const int row0 = blockIdx.y * 128;
    const int col0 = blockIdx.x * 128;
    const int dir = col0 >> 10, gi0 = col0 & 1023;
    const int wm = wid >> 2, wn = wid & 3;

    if (tid < 128) {
        int g = col0 + tid;
        sbias[tid] = (g < 1024) ? b_f[g] : b_b[g - 1024];
    }

    float acc[4][4][4];
#pragma unroll
    for (int i = 0; i < 4; ++i)
#pragma unroll
        for (int j = 0; j < 4; ++j)
#pragma unroll
            for (int e = 0; e < 4; ++e) acc[i][j][e] = 0.f;

    for (int kc = 0; kc < 4; ++kc) {
        __syncthreads();
        {
            int r  = tid >> 1;
            int g2 = (tid & 1) * 4;
            size_t abase = (size_t)(row0 + r) * 256 + kc * 64 + g2 * 8;
            size_t bbase = (size_t)(col0 + r) * 256 + kc * 64 + g2 * 8;
            int so = r * K1_STR + g2 * 8;
#pragma unroll
            for (int i = 0; i < 4; ++i) {
                *(uint4*)(smb + K1_AHI + so + i * 8) = *(const uint4*)(g_ahi + abase + i * 8);
                *(uint4*)(smb + K1_ALO + so + i * 8) = *(const uint4*)(g_alo + abase + i * 8);
                *(uint4*)(smb + K1_BHI + so + i * 8) = *(const uint4*)(g_bhi + bbase + i * 8);
                *(uint4*)(smb + K1_BLO + so + i * 8) = *(const uint4*)(g_blo + bbase + i * 8);
            }
        }
        __syncthreads();

#pragma unroll
        for (int ks = 0; ks < 4; ++ks) {
            uint32_t bh[4][2], bl[4][2];
#pragma unroll
            for (int nf = 0; nf < 4; ++nf) {
                int nrow = wn * 32 + nf * 8 + (lane & 7);
                int kof  = ks * 16 + ((lane >> 3) & 1) * 8;
                LDSM_X2(bh[nf], sA + (uint32_t)(K1_BHI + nrow * K1_STR + kof) * 2);
                LDSM_X2(bl[nf], sA + (uint32_t)(K1_BLO + nrow * K1_STR + kof) * 2);
            }
            uint32_t af[4][4];
            {
                int mrow = wm * 64 + (lane & 15);
                int kof  = ks * 16 + (lane >> 4) * 8;
#pragma unroll
                for (int mf = 0; mf < 4; ++mf)
                    LDSM_X4(af[mf], sA + (uint32_t)(K1_AHI + (mrow + mf * 16) * K1_STR + kof) * 2);
#pragma unroll
                for (int mf = 0; mf < 4; ++mf)
#pragma unroll
                    for (int nf = 0; nf < 4; ++nf) {
                        mma16816(acc[mf][nf], af[mf], bh[nf]);
                        mma16816(acc[mf][nf], af[mf], bl[nf]);
                    }
#pragma unroll
                for (int mf = 0; mf < 4; ++mf)
                    LDSM_X4(af[mf], sA + (uint32_t)(K1_ALO + (mrow + mf * 16) * K1_STR + kof) * 2);
#pragma unroll
                for (int mf = 0; mf < 4; ++mf)
#pragma unroll
                    for (int nf = 0; nf < 4; ++nf)
                        mma16816(acc[mf][nf], af[mf], bh[nf]);
            }
        }
    }

    const int gq = lane >> 2, tq = lane & 3;
#pragma unroll
    for (int mf = 0; mf < 4; ++mf)
#pragma unroll
        for (int i2 = 0; i2 < 2; ++i2) {
            int m = wm * 64 + mf * 16 + gq + i2 * 8;
            int r = row0 + m;
            int t = r >> 6, b = r & 63;
            float* dst = g_xw + (((size_t)dir * T_ + t) * B_ + b) * 1024 + gi0;
#pragma unroll
            for (int nf = 0; nf < 4; ++nf) {
                int n = wn * 32 + nf * 8 + tq * 2;
                float2 v;
                v.x = acc[mf][nf][i2 * 2 + 0] + sbias[n];
                v.y = acc[mf][nf][i2 * 2 + 1] + sbias[n + 1];
                *(float2*)(dst + n) = v;
            }
        }
}

// =========================================================================
// K2: BiLSTM recurrence, tensor cores + DSMEM exchange.
// NEW: split-K warp layout (2 kh x 4 nq; warp = n32 x k128) halves A-tile
// SMEM reads; partials combined via doubled gate-scatter slots.
// NEW: bulk mbarrier arrive (fence.acq_rel.cluster + lane0 count-32).
// =========================================================================
#define W_STR 264
#define OFF_WHI  0
#define OFF_WLO  33792
#define OFF_A0HI 67584
#define BY_SG    168960
#define SG_SLOT  1088
#define BY_MSK   (BY_SG + 8704)
#define BY_STG   (BY_MSK + 4096)
#define BY_MBAR  (BY_STG + 1024)
#define BY_MAX   (BY_MBAR + 16)
#define K2_SMEM  (BY_MAX + 16)

__device__ __forceinline__ float fsig(float x) { return 1.f / (1.f + __expf(-x)); }

__global__ __launch_bounds__(256, 1) __cluster_dims__(8, 1, 1)
void k2_lstm(const float* __restrict__ Whh_f, const float* __restrict__ Whh_b,
             const int* __restrict__ mask)
{
    __nv_bfloat16* SM = (__nv_bfloat16*)dyn_smem;
    float* sg  = (float*)(dyn_smem + BY_SG);    // [2 kh][4 g][8 b][34]
    char*  msk = dyn_smem + BY_MSK;             // [8 b][512]
    __nv_bfloat16* stgH = (__nv_bfloat16*)(dyn_smem + BY_STG);
    __nv_bfloat16* stgL = (__nv_bfloat16*)(dyn_smem + BY_STG + 512);
    int* smax = (int*)(dyn_smem + BY_MAX);
    const uint32_t sb = smem_u32(dyn_smem);

    const int tid  = threadIdx.x;
    const int wid  = tid >> 5;
    const int lane = tid & 31;
    const int rank = blockIdx.x & 7;
    const int cid  = blockIdx.x >> 3;
    const int d    = cid >> 3;
    const int G    = cid & 7;
    const int cb = tid >> 5;
    const int cj = tid & 31;
    const int jg = 32 * rank + cj;
    const int bg = 8 * G + cb;

    // split-K warp roles
    const int kh = wid & 1;         // K half
    const int nq = wid >> 1;        // gate (n32 block)

    if (tid == 0) {
        MBAR_INIT(sb + BY_MBAR, 256);
        MBAR_INIT(sb + BY_MBAR + 8, 256);
        *smax = 0;
    }
    {
        const float* Whh = d ? Whh_b : Whh_f;
        for (int n = wid; n < 128; n += 8) {
            const float* row = Whh + (size_t)((n >> 5) * 256 + 32 * rank + (n & 31)) * 256;
#pragma unroll
            for (int k0 = lane * 4; k0 < 256; k0 += 128) {
                float4 v = *(const float4*)(row + k0);
                __nv_bfloat162 h0 = __floats2bfloat162_rn(v.x, v.y);
                __nv_bfloat162 h1 = __floats2bfloat162_rn(v.z, v.w);
                __nv_bfloat162 l0 = __floats2bfloat162_rn(v.x - __bfloat162float(h0.x),
                                                          v.y - __bfloat162float(h0.y));
                __nv_bfloat162 l1 = __floats2bfloat162_rn(v.z - __bfloat162float(h1.x),
                                                          v.w - __bfloat162float(h1.y));
                *(uint2*)(SM + OFF_WHI + n * W_STR + k0) = make_uint2(*(uint32_t*)&h0, *(uint32_t*)&h1);
                *(uint2*)(SM + OFF_WLO + n * W_STR + k0) = make_uint2(*(uint32_t*)&l0, *(uint32_t*)&l1);
            }
        }
        __nv_bfloat16 z = __float2bfloat16(0.f);
        for (int u = tid; u < 16896; u += 256)
            SM[OFF_A0HI + u] = z;
        for (int u = tid; u < 4096; u += 256)
            msk[u] = (char)mask[(8 * G + (u >> 9)) * T_ + (u & 511)];
    }
    __syncthreads();
    {
        int part = (int)msk[tid] + (int)msk[256 + tid];
#pragma unroll
        for (int o = 16; o; o >>= 1) part += __shfl_xor_sync(0xffffffffu, part, o);
        if (lane == 0) atomicAdd(smax, part);
    }
    __syncthreads();
    const int maxlen = *smax;

    // ---- hoist W fragments: warp covers n32 (gate nq), k128 (half kh) ----
    const int brow8 = nq * 32 + (lane & 7);
    const int bk8   = kh * 128 + ((lane >> 3) & 1) * 8;
    uint32_t rbh[8][8], rbl[8][8];
#pragma unroll
    for (int ks = 0; ks < 8; ++ks) {
        const int k = ks * 16;
#pragma unroll
        for (int f = 0; f < 4; ++f) {
            LDSM_X2(&rbh[ks][f * 2], sb + (uint32_t)(OFF_WHI + (brow8 + f * 8) * W_STR + bk8 + k) * 2);
            LDSM_X2(&rbl[ks][f * 2], sb + (uint32_t)(OFF_WLO + (brow8 + f * 8) * W_STR + bk8 + k) * 2);
        }
    }

    asm volatile("barrier.cluster.arrive.aligned;" ::: "memory");
    asm volatile("barrier.cluster.wait.aligned;"   ::: "memory");

    const int dt = d ? -1 : 1;
    int t = d ? (maxlen - 1) : 0;

    if (d == 1) {
        for (int tt = maxlen; tt < T_; ++tt)
            g_h[(((size_t)1 * T_ + tt) * B_ + bg) * HD_ + jg] = 0.f;
    }

    float c = 0.f, h = 0.f;
    float px[4];
    {
        const float* xp = g_xw + (((size_t)d * T_ + t) * B_ + bg) * 1024 + jg;
        px[0] = xp[0]; px[1] = xp[256]; px[2] = xp[512]; px[3] = xp[768];
    }

    const int mrow = lane & 15;
    const int ak   = kh * 128 + (lane >> 4) * 8;
    const int gq = lane >> 2, tq = lane & 3;
    float* sgk = sg + kh * SG_SLOT;
    int ph0 = 0, ph1 = 0;

    for (int s = 0; s < maxlen; ++s) {
        const int buf  = s & 1;
        const int nbuf = buf ^ 1;
        const int a_hi = OFF_A0HI + buf * 8448;
        const int a_lo = a_hi + 4224;

        // prefetch next step's xw BEFORE the exchange wait
        float nx[4];
        {
            int tn = (s + 1 < maxlen) ? t + dt : t;
            const float* xp = g_xw + (((size_t)d * T_ + tn) * B_ + bg) * 1024 + jg;
            nx[0] = xp[0]; nx[1] = xp[256]; nx[2] = xp[512]; nx[3] = xp[768];
        }
        if (s > 0) {
            uint32_t mb = sb + BY_MBAR + buf * 8;
            if (buf) { mbar_wait_cl(mb, (uint32_t)ph1); ph1 ^= 1; }
            else     { mbar_wait_cl(mb, (uint32_t)ph0); ph0 ^= 1; }
        }

        // ---- tensor-core gate GEMM: warp = n32 x k128, 3 passes ----
        float acc[4][4];
#pragma unroll
        for (int f = 0; f < 4; ++f)
#pragma unroll
            for (int e = 0; e < 4; ++e) acc[f][e] = 0.f;
#pragma unroll
        for (int ks = 0; ks < 8; ++ks) {
            const int k = ks * 16;
            uint32_t ah[4], al[4];
            LDSM_X4(ah, sb + (uint32_t)(a_hi + mrow * W_STR + ak + k) * 2);
            LDSM_X4(al, sb + (uint32_t)(a_lo + mrow * W_STR + ak + k) * 2);
#pragma unroll
            for (int f = 0; f < 4; ++f) {
                mma16816(acc[f], ah, &rbh[ks][f * 2]);
                mma16816(acc[f], ah, &rbl[ks][f * 2]);
                mma16816(acc[f], al, &rbh[ks][f * 2]);
            }
        }

        // ---- scatter gate partials: slot kh, gate nq, rows 0..7 real ----
#pragma unroll
        for (int f = 0; f < 4; ++f) {
            int j = f * 8 + tq * 2;
            sgk[(nq * 8 + gq) * 34 + j]     = acc[f][0];
            sgk[(nq * 8 + gq) * 34 + j + 1] = acc[f][1];
        }
        __syncthreads();

        // ---- cell update (1 cell per thread): add both K-half partials ----
        {
            int m = msk[cb * 512 + t];
            float zi = sg[(0 * 8 + cb) * 34 + cj] + sg[SG_SLOT + (0 * 8 + cb) * 34 + cj] + px[0];
            float zf = sg[(1 * 8 + cb) * 34 + cj] + sg[SG_SLOT + (1 * 8 + cb) * 34 + cj] + px[1];
            float zg = sg[(2 * 8 + cb) * 34 + cj] + sg[SG_SLOT + (2 * 8 + cb) * 34 + cj] + px[2];
            float zo = sg[(3 * 8 + cb) * 34 + cj] + sg[SG_SLOT + (3 * 8 + cb) * 34 + cj] + px[3];
            float cn = fsig(zf) * c + fsig(zi) * tanhf(zg);
            float hn = fsig(zo) * tanhf(cn);
            if (m) { c = cn; h = hn; }

            g_h[(((size_t)d * T_ + t) * B_ + bg) * HD_ + jg] = h;
            __nv_bfloat16 hi = __float2bfloat16(h);
            __nv_bfloat16 lo = __float2bfloat16(h - __bfloat162float(hi));
            stgH[cb * 32 + cj] = hi;
            stgL[cb * 32 + cj] = lo;
        }
        px[0] = nx[0]; px[1] = nx[1]; px[2] = nx[2]; px[3] = nx[3];
        __syncthreads();

        // ---- DSMEM broadcast: warp w -> peer rank w; bulk arrive ----
        if (s + 1 < maxlen) {
            int r = lane >> 2, q = lane & 3;
            uint4 hv = *(const uint4*)((const char*)stgH + r * 64 + q * 16);
            uint4 lv = *(const uint4*)((const char*)stgL + r * 64 + q * 16);
            uint32_t dh = sb + (uint32_t)(OFF_A0HI + nbuf * 8448 + r * W_STR + 32 * rank + q * 8) * 2;
            uint32_t dl = dh + 4224 * 2;
            uint32_t mb = sb + BY_MBAR + nbuf * 8;
            uint32_t rdh = mapa_rank(dh, (uint32_t)wid);
            uint32_t rdl = mapa_rank(dl, (uint32_t)wid);
            uint32_t rmb = mapa_rank(mb, (uint32_t)wid);
            STS_CL_V4(rdh, hv);
            STS_CL_V4(rdl, lv);
            asm volatile("fence.acq_rel.cluster;" ::: "memory");
            __syncwarp();
            if (lane == 0)
                asm volatile(
                    "mbarrier.arrive.release.cluster.shared::cluster.b64 _, [%0], %1;"
                    :: "r"(rmb), "r"(32u) : "memory");
        }
        t += dt;
    }

    if (d == 0) {
        for (int tt = maxlen; tt < T_; ++tt)
            g_h[(((size_t)0 * T_ + tt) * B_ + bg) * HD_ + jg] = h;
    }

    asm volatile("barrier.cluster.arrive.aligned;" ::: "memory");
    asm volatile("barrier.cluster.wait.aligned;"   ::: "memory");
}

// =========================================================================
// K3: W_tag transpose
// =========================================================================
__global__ void k3_wt(const float* __restrict__ W_tag)
{
    int kk = threadIdx.x;
    for (int k = 0; k < 32; ++k)
        g_Wt[kk * 32 + k] = W_tag[k * 512 + kk];
}

// =========================================================================
// K4: h_tag = [h_f,h_b] @ W_tag^T + b_tag. 4 independent accumulators.
// =========================================================================
__global__ __launch_bounds__(256) void k4_htag(const float* __restrict__ b_tag)
{
    __shared__ float hrow[8][512];
    const int tid = threadIdx.x;
    const int r0 = blockIdx.x * 8;

    for (int u = tid; u < 1024; u += 256) {
        int rl = u >> 7;
        int off = (u & 127) * 4;
        int r = r0 + rl;
        int t = r >> 6, b = r & 63;
        const float* src = (off < 256)
            ? &g_h[(((size_t)0 * T_ + t) * B_ + b) * HD_ + off]
            : &g_h[(((size_t)1 * T_ + t) * B_ + b) * HD_ + off - 256];
        *(float4*)&hrow[rl][off] = *(const float4*)src;
    }
    __syncthreads();

    const int rl = tid >> 5;
    const int k  = tid & 31;
    float a0 = b_tag[k], a1 = 0.f, a2 = 0.f, a3 = 0.f;
#pragma unroll 4
    for (int kk = 0; kk < 512; kk += 4) {
        a0 = fmaf(hrow[rl][kk + 0], g_Wt[(kk + 0) * 32 + k], a0);
        a1 = fmaf(hrow[rl][kk + 1], g_Wt[(kk + 1) * 32 + k], a1);
        a2 = fmaf(hrow[rl][kk + 2], g_Wt[(kk + 2) * 32 + k], a2);
        a3 = fmaf(hrow[rl][kk + 3], g_Wt[(kk + 3) * 32 + k], a3);
    }
    g_htag[(size_t)(r0 + rl) * 32 + k] = (a0 + a1) + (a2 + a3);
}

// =========================================================================
// K5: CRF forward + gold score (R12/R14 exact per-k tree LSE; unchanged).
// =========================================================================
__global__ __launch_bounds__(32) void k5_crf(
    const int* __restrict__ mask, const int* __restrict__ gold,
    const float* __restrict__ trans, float* __restrict__ out)
{
    __shared__ unsigned mw[16];
    const int b = blockIdx.x;
    const int k = threadIdx.x;

    float trow[32];
#pragma unroll
    for (int j = 0; j < 32; ++j) trow[j] = trans[k * 32 + j];

    for (int blk = 0; blk < 16; ++blk) {
        int bit = mask[b * T_ + blk * 32 + k];
        unsigned wword = __ballot_sync(0xffffffffu, bit != 0);
        if (k == 0) mw[blk] = wword;
    }
    __syncwarp();

    float score = (k == STOP_) ? 0.f : -10000.f;
    float emit = g_htag[((size_t)0 * B_ + b) * 32 + k];

    for (int t = 0; t < T_; ++t) {
        int tn = (t + 1 < T_) ? t + 1 : t;
        float emit_n = g_htag[((size_t)tn * B_ + b) * 32 + k];
        int m = (mw[t >> 5] >> (t & 31)) & 1;

        float v[32];
#pragma unroll
        for (int j = 0; j < 32; ++j)
            v[j] = __shfl_sync(0xffffffffu, score, j) + trow[j];

        float m16[16], m8[8], m4[4], m2[2];
#pragma unroll
        for (int j = 0; j < 16; ++j) m16[j] = fmaxf(v[j], v[j + 16]);
#pragma unroll
        for (int j = 0; j < 8; ++j)  m8[j] = fmaxf(m16[j], m16[j + 8]);
#pragma unroll
        for (int j = 0; j < 4; ++j)  m4[j] = fmaxf(m8[j], m8[j + 4]);
        m2[0] = fmaxf(m4[0], m4[2]); m2[1] = fmaxf(m4[1], m4[3]);
        float mx = fmaxf(m2[0], m2[1]);

        float e[32];
#pragma unroll
        for (int j = 0; j < 32; ++j) e[j] = __expf(v[j] - mx);
        float s16[16], s8[8], s4[4], s2[2];
#pragma unroll
        for (int j = 0; j < 16; ++j) s16[j] = e[j] + e[j + 16];
#pragma unroll
        for (int j = 0; j < 8; ++j)  s8[j] = s16[j] + s16[j + 8];
#pragma unroll
        for (int j = 0; j < 4; ++j)  s4[j] = s8[j] + s8[j + 4];
        s2[0] = s4[0] + s4[2]; s2[1] = s4[1] + s4[3];
        float sum = s2[0] + s2[1];

        float sn = emit + mx + __logf(sum);
        score = m ? sn : score;
        emit = emit_n;
    }

    float zt = score + trans[STOP_ * 32 + k];
    float mx = zt;
#pragma unroll
    for (int o = 16; o; o >>= 1) mx = fmaxf(mx, __shfl_xor_sync(0xffffffffu, mx, o));
    float es = __expf(zt - mx);
#pragma unroll
    for (int o = 16; o; o >>= 1) es += __shfl_xor_sync(0xffffffffu, es, o);
    float Z = mx + __logf(es);

    float gs = 0.f;
    int len = 0;
    for (int i = k; i < T_; i += 32) {
        int m = mask[b * T_ + i];
        len += m;
        if (i < T_ - 1 && m) {
            int g1 = gold[b * T_ + i + 1];
            int g0 = gold[b * T_ + i];
            gs += g_htag[((size_t)i * B_ + b) * 32 + g1] + trans[g1 * 32 + g0];
        }
    }
#pragma unroll
    for (int o = 16; o; o >>= 1) {
        gs  += __shfl_xor_sync(0xffffffffu, gs, o);
        len += __shfl_xor_sync(0xffffffffu, len, o);
    }
    if (k == 0) {
        int last = gold[b * T_ + len - 1];
        out[b] = Z - (gs + trans[STOP_ * 32 + last]);
    }
}

// =========================================================================
extern "C" void kernel_launch(void* const* d_in, const int* in_sizes, int n_in,
                              void* d_out, int out_size)
{
    const int*   inp   = (const int*)  d_in[0];
    const int*   gold  = (const int*)  d_in[1];
    const int*   mask  = (const int*)  d_in[2];
    const float* emb   = (const float*)d_in[3];
    const float* Wih_f = (const float*)d_in[4];
    const float* Whh_f = (const float*)d_in[5];
    const float* b_f   = (const float*)d_in[6];
    const float* Wih_b = (const float*)d_in[7];
    const float* Whh_b = (const float*)d_in[8];
    const float* b_b   = (const float*)d_in[9];
    const float* W_tag = (const float*)d_in[10];
    const float* b_tag = (const float*)d_in[11];
    const float* trans = (const float*)d_in[12];
    float* out = (float*)d_out;
    (void)in_sizes; (void)n_in; (void)out_size;

    cudaFuncSetAttribute(k1_mma,  cudaFuncAttributeMaxDynamicSharedMemorySize, K1_SMEM);
    cudaFuncSetAttribute(k2_lstm, cudaFuncAttributeMaxDynamicSharedMemorySize, K2_SMEM);

    k0_conv<<<8704, 256>>>(inp, emb, Wih_f, Wih_b);
    k3_wt<<<1, 512>>>(W_tag);
    k1_mma<<<dim3(16, 256), 256, K1_SMEM>>>(b_f, b_b);
    k2_lstm<<<128, 256, K2_SMEM>>>(Whh_f, Whh_b, mask);
    k4_htag<<<(T_ * B_) / 8, 256>>>(b_tag);
    k5_crf<<<B_, 32>>>(mask, gold, trans, out);
}

// round 16
// speedup vs baseline: 1.0581x; 1.0581x over previous
#include <cuda_runtime.h>
#include <cuda_bf16.h>
#include <cstdint>
#include <cstddef>

#define T_ 512
#define B_ 64
#define HD_ 256
#define STOP_ 30

// single dynamic-smem symbol
extern __shared__ __align__(16) char dyn_smem[];

// ---------------- device scratch ----------------
__device__ float g_xw[(size_t)2 * T_ * B_ * 1024];   // [dir][t][b][4H]
__device__ float g_h[(size_t)2 * T_ * B_ * HD_];     // [dir][t][b][H]
__device__ float g_htag[(size_t)T_ * B_ * 32];
__device__ float g_Wt[512 * 32];
__device__ __nv_bfloat16 g_ahi[(size_t)32768 * 256];
__device__ __nv_bfloat16 g_alo[(size_t)32768 * 256];
__device__ __nv_bfloat16 g_bhi[(size_t)2048 * 256];
__device__ __nv_bfloat16 g_blo[(size_t)2048 * 256];

// ---------------- PTX helpers ----------------
__device__ __forceinline__ uint32_t smem_u32(const void* p) {
    uint32_t a;
    asm("{ .reg .u64 t; cvta.to.shared.u64 t, %1; cvt.u32.u64 %0, t; }" : "=r"(a) : "l"(p));
    return a;
}
#define LDSM_X4(r, addr) \
    asm volatile("ldmatrix.sync.aligned.m8n8.x4.shared.b16 {%0,%1,%2,%3}, [%4];" \
        : "=r"((r)[0]), "=r"((r)[1]), "=r"((r)[2]), "=r"((r)[3]) : "r"(addr))
#define LDSM_X2(r, addr) \
    asm volatile("ldmatrix.sync.aligned.m8n8.x2.shared.b16 {%0,%1}, [%2];" \
        : "=r"((r)[0]), "=r"((r)[1]) : "r"(addr))
__device__ __forceinline__ void mma16816(float* c, const uint32_t* a, const uint32_t* b) {
    asm volatile("mma.sync.aligned.m16n8k16.row.col.f32.bf16.bf16.f32 "
        "{%0,%1,%2,%3}, {%4,%5,%6,%7}, {%8,%9}, {%0,%1,%2,%3};"
        : "+f"(c[0]), "+f"(c[1]), "+f"(c[2]), "+f"(c[3])
        : "r"(a[0]), "r"(a[1]), "r"(a[2]), "r"(a[3]), "r"(b[0]), "r"(b[1]));
}
#define MBAR_INIT(mb, c) asm volatile("mbarrier.init.shared.b64 [%0], %1;" :: "r"(mb), "r"((uint32_t)(c)) : "memory")
__device__ __forceinline__ void mbar_wait_cl(uint32_t mb, uint32_t parity) {
    asm volatile(
        "{\n\t.reg .pred P;\n\t"
        "WL_%=:\n\t"
        "mbarrier.try_wait.parity.acquire.cluster.shared::cta.b64 P, [%0], %1, 0x989680;\n\t"
        "@P bra WD_%=;\n\t"
        "bra WL_%=;\n\t"
        "WD_%=:\n\t}"
        :: "r"(mb), "r"(parity) : "memory");
}
__device__ __forceinline__ uint32_t mapa_rank(uint32_t a, uint32_t r) {
    uint32_t o;
    asm("mapa.shared::cluster.u32 %0, %1, %2;" : "=r"(o) : "r"(a), "r"(r));
    return o;
}
#define STS_CL_V4(addr, v) \
    asm volatile("st.shared::cluster.v4.b32 [%0], {%1,%2,%3,%4};" \
        :: "r"(addr), "r"((v).x), "r"((v).y), "r"((v).z), "r"((v).w) : "memory")
#define MBAR_ARRIVE_REMOTE(addr) \
    asm volatile("mbarrier.arrive.release.cluster.shared::cluster.b64 _, [%0];" :: "r"(addr) : "memory")

// =========================================================================
// K0: gather emb rows + split-convert A and B to bf16 hi/lo. (unchanged)
// =========================================================================
__global__ __launch_bounds__(256) void k0_conv(
    const int* __restrict__ inp, const float* __restrict__ emb,
    const float* __restrict__ Wih_f, const float* __restrict__ Wih_b)
{
    size_t u = (size_t)blockIdx.x * 256 + threadIdx.x;
    const float* src;
    __nv_bfloat16 *dhi, *dlo;
    size_t off;
    if (u < 2097152) {
        int r = (int)(u >> 6);
        int q = (int)(u & 63);
        int tok = inp[(r & 63) * T_ + (r >> 6)];
        src = emb + (size_t)tok * 256 + q * 4;
        off = (size_t)r * 256 + q * 4;
        dhi = g_ahi; dlo = g_alo;
    } else {
        size_t v = u - 2097152;
        if (v >= 131072) return;
        int r = (int)(v >> 6);
        int q = (int)(v & 63);
        src = (r < 1024 ? Wih_f + (size_t)r * 256
                        : Wih_b + (size_t)(r - 1024) * 256) + q * 4;
        off = (size_t)r * 256 + q * 4;
        dhi = g_bhi; dlo = g_blo;
    }
    float4 a = *(const float4*)src;
    __nv_bfloat162 h0 = __floats2bfloat162_rn(a.x, a.y);
    __nv_bfloat162 h1 = __floats2bfloat162_rn(a.z, a.w);
    __nv_bfloat162 l0 = __floats2bfloat162_rn(a.x - __bfloat162float(h0.x),
                                              a.y - __bfloat162float(h0.y));
    __nv_bfloat162 l1 = __floats2bfloat162_rn(a.z - __bfloat162float(h1.x),
                                              a.w - __bfloat162float(h1.y));
    *(uint2*)(dhi + off) = make_uint2(*(uint32_t*)&h0, *(uint32_t*)&h1);
    *(uint2*)(dlo + off) = make_uint2(*(uint32_t*)&l0, *(uint32_t*)&l1);
}

// =========================================================================
// K1: xW = A @ B^T + bias via mma.sync bf16 split (unchanged).
// =========================================================================
#define K1_STR  72
#define K1_AHI  0
#define K1_ALO  (128 * K1_STR)
#define K1_BHI  (2 * 128 * K1_STR)
#define K1_BLO  (3 * 128 * K1_STR)
#define K1_BIAS_B (4 * 128 * K1_STR * 2)
#define K1_SMEM (K1_BIAS_B + 512 + 128)

__global__ __launch_bounds__(256, 2) void k1_mma(
    const float* __restrict__ b_f, const float* __restrict__ b_b)
{
    __nv_bfloat16* smb = (__nv_bfloat16*)dyn_smem;
    float* sbias = (float*)(dyn_smem + K1_BIAS_B);
    const uint32_t sA = smem_u32(smb);
    const int tid = threadIdx.x;
    const int wid = tid >> 5, lane = tid & 31;
    const int row0 = blockIdx.y * 128;
    const int col0 = blockIdx.x * 128;
    const int dir = col0 >> 10, gi0 = col0 & 1023;
    const int wm = wid >> 2, wn = wid & 3;

    if (tid < 128) {
        int g = col0 + tid;
        sbias[tid] = (g < 1024) ? b_f[g] : b_b[g - 1024];
    }

    float acc[4][4][4];
#pragma unroll
    for (int i = 0; i < 4; ++i)
#pragma unroll
        for (int j = 0; j < 4; ++j)
#pragma unroll
            for (int e = 0; e < 4; ++e) acc[i][j][e] = 0.f;

    for (int kc = 0; kc < 4; ++kc) {
        __syncthreads();
        {
            int r  = tid >> 1;
            int g2 = (tid & 1) * 4;
            size_t abase = (size_t)(row0 + r) * 256 + kc * 64 + g2 * 8;
            size_t bbase = (size_t)(col0 + r) * 256 + kc * 64 + g2 * 8;
            int so = r * K1_STR + g2 * 8;
#pragma unroll
            for (int i = 0; i < 4; ++i) {
                *(uint4*)(smb + K1_AHI + so + i * 8) = *(const uint4*)(g_ahi + abase + i * 8);
                *(uint4*)(smb + K1_ALO + so + i * 8) = *(const uint4*)(g_alo + abase + i * 8);
                *(uint4*)(smb + K1_BHI + so + i * 8) = *(const uint4*)(g_bhi + bbase + i * 8);
                *(uint4*)(smb + K1_BLO + so + i * 8) = *(const uint4*)(g_blo + bbase + i * 8);
            }
        }
        __syncthreads();

#pragma unroll
        for (int ks = 0; ks < 4; ++ks) {
            uint32_t bh[4][2], bl[4][2];
#pragma unroll
            for (int nf = 0; nf < 4; ++nf) {
                int nrow = wn * 32 + nf * 8 + (lane & 7);
                int kof  = ks * 16 + ((lane >> 3) & 1) * 8;
                LDSM_X2(bh[nf], sA + (uint32_t)(K1_BHI + nrow * K1_STR + kof) * 2);
                LDSM_X2(bl[nf], sA + (uint32_t)(K1_BLO + nrow * K1_STR + kof) * 2);
            }
            uint32_t af[4][4];
            {
                int mrow = wm * 64 + (lane & 15);
                int kof  = ks * 16 + (lane >> 4) * 8;
#pragma unroll
                for (int mf = 0; mf < 4; ++mf)
                    LDSM_X4(af[mf], sA + (uint32_t)(K1_AHI + (mrow + mf * 16) * K1_STR + kof) * 2);
#pragma unroll
                for (int mf = 0; mf < 4; ++mf)
#pragma unroll
                    for (int nf = 0; nf < 4; ++nf) {
                        mma16816(acc[mf][nf], af[mf], bh[nf]);
                        mma16816(acc[mf][nf], af[mf], bl[nf]);
                    }
#pragma unroll
                for (int mf = 0; mf < 4; ++mf)
                    LDSM_X4(af[mf], sA + (uint32_t)(K1_ALO + (mrow + mf * 16) * K1_STR + kof) * 2);
#pragma unroll
                for (int mf = 0; mf < 4; ++mf)
#pragma unroll
                    for (int nf = 0; nf < 4; ++nf)
                        mma16816(acc[mf][nf], af[mf], bh[nf]);
            }
        }
    }

    const int gq = lane >> 2, tq = lane & 3;
#pragma unroll
    for (int mf = 0; mf < 4; ++mf)
#pragma unroll
        for (int i2 = 0; i2 < 2; ++i2) {
            int m = wm * 64 + mf * 16 + gq + i2 * 8;
            int r = row0 + m;
            int t = r >> 6, b = r & 63;
            float* dst = g_xw + (((size_t)dir * T_ + t) * B_ + b) * 1024 + gi0;
#pragma unroll
            for (int nf = 0; nf < 4; ++nf) {
                int n = wn * 32 + nf * 8 + tq * 2;
                float2 v;
                v.x = acc[mf][nf][i2 * 2 + 0] + sbias[n];
                v.y = acc[mf][nf][i2 * 2 + 1] + sbias[n + 1];
                *(float2*)(dst + n) = v;
            }
        }
}

// =========================================================================
// K2: BiLSTM recurrence, tensor cores + DSMEM exchange, W frags in regs.
// REVERTED exactly to the R14 version (best passing).
// =========================================================================
#define W_STR 264
#define OFF_WHI  0
#define OFF_WLO  33792
#define OFF_A0HI 67584
#define BY_SG    168960
#define BY_MSK   173312
#define BY_STG   177408
#define BY_MBAR  178432
#define BY_MAX   178448
#define K2_SMEM  178464

__device__ __forceinline__ float fsig(float x) { return 1.f / (1.f + __expf(-x)); }

__global__ __launch_bounds__(256, 1) __cluster_dims__(8, 1, 1)
void k2_lstm(const float* __restrict__ Whh_f, const float* __restrict__ Whh_b,
             const int* __restrict__ mask)
{
    __nv_bfloat16* SM = (__nv_bfloat16*)dyn_smem;
    float* sg  = (float*)(dyn_smem + BY_SG);    // [4 g][8 b][34]
    char*  msk = dyn_smem + BY_MSK;             // [8 b][512]
    __nv_bfloat16* stgH = (__nv_bfloat16*)(dyn_smem + BY_STG);
    __nv_bfloat16* stgL = (__nv_bfloat16*)(dyn_smem + BY_STG + 512);
    int* smax = (int*)(dyn_smem + BY_MAX);
    const uint32_t sb = smem_u32(dyn_smem);

    const int tid  = threadIdx.x;
    const int wid  = tid >> 5;
    const int lane = tid & 31;
    const int rank = blockIdx.x & 7;
    const int cid  = blockIdx.x >> 3;
    const int d    = cid >> 3;
    const int G    = cid & 7;
    const int cb = tid >> 5;
    const int cj = tid & 31;
    const int jg = 32 * rank + cj;
    const int bg = 8 * G + cb;

    if (tid == 0) {
        MBAR_INIT(sb + BY_MBAR, 256);
        MBAR_INIT(sb + BY_MBAR + 8, 256);
        *smax = 0;
    }
    {
        const float* Whh = d ? Whh_b : Whh_f;
        for (int n = wid; n < 128; n += 8) {
            const float* row = Whh + (size_t)((n >> 5) * 256 + 32 * rank + (n & 31)) * 256;
#pragma unroll
            for (int k0 = lane * 4; k0 < 256; k0 += 128) {
                float4 v = *(const float4*)(row + k0);
                __nv_bfloat162 h0 = __floats2bfloat162_rn(v.x, v.y);
                __nv_bfloat162 h1 = __floats2bfloat162_rn(v.z, v.w);
                __nv_bfloat162 l0 = __floats2bfloat162_rn(v.x - __bfloat162float(h0.x),
                                                          v.y - __bfloat162float(h0.y));
                __nv_bfloat162 l1 = __floats2bfloat162_rn(v.z - __bfloat162float(h1.x),
                                                          v.w - __bfloat162float(h1.y));
                *(uint2*)(SM + OFF_WHI + n * W_STR + k0) = make_uint2(*(uint32_t*)&h0, *(uint32_t*)&h1);
                *(uint2*)(SM + OFF_WLO + n * W_STR + k0) = make_uint2(*(uint32_t*)&l0, *(uint32_t*)&l1);
            }
        }
        __nv_bfloat16 z = __float2bfloat16(0.f);
        for (int u = tid; u < 16896; u += 256)
            SM[OFF_A0HI + u] = z;
        for (int u = tid; u < 4096; u += 256)
            msk[u] = (char)mask[(8 * G + (u >> 9)) * T_ + (u & 511)];
    }
    __syncthreads();
    {
        int part = (int)msk[tid] + (int)msk[256 + tid];
#pragma unroll
        for (int o = 16; o; o >>= 1) part += __shfl_xor_sync(0xffffffffu, part, o);
        if (lane == 0) atomicAdd(smax, part);
    }
    __syncthreads();
    const int maxlen = *smax;

    // ---- hoist W fragments (hi+lo, all 16 k-steps) into registers ----
    const int brow = wid * 16 + (lane & 7);
    const int bkof = ((lane >> 3) & 1) * 8;
    uint32_t rbh[16][4], rbl[16][4];
#pragma unroll
    for (int ks = 0; ks < 16; ++ks) {
        const int k = ks * 16;
        LDSM_X2(&rbh[ks][0], sb + (uint32_t)(OFF_WHI + brow * W_STR + k + bkof) * 2);
        LDSM_X2(&rbh[ks][2], sb + (uint32_t)(OFF_WHI + (brow + 8) * W_STR + k + bkof) * 2);
        LDSM_X2(&rbl[ks][0], sb + (uint32_t)(OFF_WLO + brow * W_STR + k + bkof) * 2);
        LDSM_X2(&rbl[ks][2], sb + (uint32_t)(OFF_WLO + (brow + 8) * W_STR + k + bkof) * 2);
    }

    asm volatile("barrier.cluster.arrive.aligned;" ::: "memory");
    asm volatile("barrier.cluster.wait.aligned;"   ::: "memory");

    const int dt = d ? -1 : 1;
    int t = d ? (maxlen - 1) : 0;

    if (d == 1) {
        for (int tt = maxlen; tt < T_; ++tt)
            g_h[(((size_t)1 * T_ + tt) * B_ + bg) * HD_ + jg] = 0.f;
    }

    float c = 0.f, h = 0.f;
    float px[4];
    {
        const float* xp = g_xw + (((size_t)d * T_ + t) * B_ + bg) * 1024 + jg;
        px[0] = xp[0]; px[1] = xp[256]; px[2] = xp[512]; px[3] = xp[768];
    }

    const int mrow = lane & 15;
    const int akof = (lane >> 4) * 8;
    const int gq = lane >> 2, tq = lane & 3;
    int ph0 = 0, ph1 = 0;

    for (int s = 0; s < maxlen; ++s) {
        const int buf  = s & 1;
        const int nbuf = buf ^ 1;
        const int a_hi = OFF_A0HI + buf * 8448;
        const int a_lo = a_hi + 4224;

        // prefetch next step's xw BEFORE the exchange wait
        float nx[4];
        {
            int tn = (s + 1 < maxlen) ? t + dt : t;
            const float* xp = g_xw + (((size_t)d * T_ + tn) * B_ + bg) * 1024 + jg;
            nx[0] = xp[0]; nx[1] = xp[256]; nx[2] = xp[512]; nx[3] = xp[768];
        }
        if (s > 0) {
            uint32_t mb = sb + BY_MBAR + buf * 8;
            if (buf) { mbar_wait_cl(mb, (uint32_t)ph1); ph1 ^= 1; }
            else     { mbar_wait_cl(mb, (uint32_t)ph0); ph0 ^= 1; }
        }

        // ---- tensor-core gate GEMM (3 passes, fp32 accum; W in regs) ----
        float acc0[4] = {0.f, 0.f, 0.f, 0.f};
        float acc1[4] = {0.f, 0.f, 0.f, 0.f};
#pragma unroll
        for (int ks = 0; ks < 16; ++ks) {
            const int k = ks * 16;
            uint32_t ah[4], al[4];
            LDSM_X4(ah, sb + (uint32_t)(a_hi + mrow * W_STR + k + akof) * 2);
            LDSM_X4(al, sb + (uint32_t)(a_lo + mrow * W_STR + k + akof) * 2);
            mma16816(acc0, ah, &rbh[ks][0]);  mma16816(acc1, ah, &rbh[ks][2]);
            mma16816(acc0, ah, &rbl[ks][0]);  mma16816(acc1, ah, &rbl[ks][2]);
            mma16816(acc0, al, &rbh[ks][0]);  mma16816(acc1, al, &rbh[ks][2]);
        }

        // ---- scatter gates (rows 0..7 real) ----
        if (gq < 8) {
            {
                int n = wid * 16 + tq * 2;
                int g = n >> 5, j = n & 31;
                sg[(g * 8 + gq) * 34 + j]     = acc0[0];
                sg[(g * 8 + gq) * 34 + j + 1] = acc0[1];
            }
            {
                int n = wid * 16 + 8 + tq * 2;
                int g = n >> 5, j = n & 31;
                sg[(g * 8 + gq) * 34 + j]     = acc1[0];
                sg[(g * 8 + gq) * 34 + j + 1] = acc1[1];
            }
        }
        __syncthreads();

        // ---- cell update (1 cell per thread) + stage h hi/lo ----
        {
            int m = msk[cb * 512 + t];
            float zi = sg[(0 * 8 + cb) * 34 + cj] + px[0];
            float zf = sg[(1 * 8 + cb) * 34 + cj] + px[1];
            float zg = sg[(2 * 8 + cb) * 34 + cj] + px[2];
            float zo = sg[(3 * 8 + cb) * 34 + cj] + px[3];
            float cn = fsig(zf) * c + fsig(zi) * tanhf(zg);
            float hn = fsig(zo) * tanhf(cn);
            if (m) { c = cn; h = hn; }

            g_h[(((size_t)d * T_ + t) * B_ + bg) * HD_ + jg] = h;
            __nv_bfloat16 hi = __float2bfloat16(h);
            __nv_bfloat16 lo = __float2bfloat16(h - __bfloat162float(hi));
            stgH[cb * 32 + cj] = hi;
            stgL[cb * 32 + cj] = lo;
        }
        px[0] = nx[0]; px[1] = nx[1]; px[2] = nx[2]; px[3] = nx[3];
        __syncthreads();

        // ---- DSMEM broadcast: warp w -> peer rank w ----
        if (s + 1 < maxlen) {
            int r = lane >> 2, q = lane & 3;
            uint4 hv = *(const uint4*)((const char*)stgH + r * 64 + q * 16);
            uint4 lv = *(const uint4*)((const char*)stgL + r * 64 + q * 16);
            uint32_t dh = sb + (uint32_t)(OFF_A0HI + nbuf * 8448 + r * W_STR + 32 * rank + q * 8) * 2;
            uint32_t dl = dh + 4224 * 2;
            uint32_t mb = sb + BY_MBAR + nbuf * 8;
            uint32_t rdh = mapa_rank(dh, (uint32_t)wid);
            uint32_t rdl = mapa_rank(dl, (uint32_t)wid);
            uint32_t rmb = mapa_rank(mb, (uint32_t)wid);
            STS_CL_V4(rdh, hv);
            STS_CL_V4(rdl, lv);
            MBAR_ARRIVE_REMOTE(rmb);
        }
        t += dt;
    }

    if (d == 0) {
        for (int tt = maxlen; tt < T_; ++tt)
            g_h[(((size_t)0 * T_ + tt) * B_ + bg) * HD_ + jg] = h;
    }

    asm volatile("barrier.cluster.arrive.aligned;" ::: "memory");
    asm volatile("barrier.cluster.wait.aligned;"   ::: "memory");
}

// =========================================================================
// K3: W_tag transpose
// =========================================================================
__global__ void k3_wt(const float* __restrict__ W_tag)
{
    int kk = threadIdx.x;
    for (int k = 0; k < 32; ++k)
        g_Wt[kk * 32 + k] = W_tag[k * 512 + kk];
}

// =========================================================================
// K4: h_tag = [h_f,h_b] @ W_tag^T + b_tag. 4 independent accumulators.
// =========================================================================
__global__ __launch_bounds__(256) void k4_htag(const float* __restrict__ b_tag)
{
    __shared__ float hrow[8][512];
    const int tid = threadIdx.x;
    const int r0 = blockIdx.x * 8;

    for (int u = tid; u < 1024; u += 256) {
        int rl = u >> 7;
        int off = (u & 127) * 4;
        int r = r0 + rl;
        int t = r >> 6, b = r & 63;
        const float* src = (off < 256)
            ? &g_h[(((size_t)0 * T_ + t) * B_ + b) * HD_ + off]
            : &g_h[(((size_t)1 * T_ + t) * B_ + b) * HD_ + off - 256];
        *(float4*)&hrow[rl][off] = *(const float4*)src;
    }
    __syncthreads();

    const int rl = tid >> 5;
    const int k  = tid & 31;
    float a0 = b_tag[k], a1 = 0.f, a2 = 0.f, a3 = 0.f;
#pragma unroll 4
    for (int kk = 0; kk < 512; kk += 4) {
        a0 = fmaf(hrow[rl][kk + 0], g_Wt[(kk + 0) * 32 + k], a0);
        a1 = fmaf(hrow[rl][kk + 1], g_Wt[(kk + 1) * 32 + k], a1);
        a2 = fmaf(hrow[rl][kk + 2], g_Wt[(kk + 2) * 32 + k], a2);
        a3 = fmaf(hrow[rl][kk + 3], g_Wt[(kk + 3) * 32 + k], a3);
    }
    g_htag[(size_t)(r0 + rl) * 32 + k] = (a0 + a1) + (a2 + a3);
}

// =========================================================================
// K5: CRF forward + gold score. Two-group LSE:
//   t=0 exact per-k (STOP-only inflow; etr underflows there).
//   t>=1: group-2 (j != PAD) via one exp/lane + shfl-FMA against
//   etr[j]=exp(trans[k][j]); PAD inflow kept as exact scalar term A;
//   combine LSE(A, B) with 2-way max shift. Exact modulo fp.
// =========================================================================
#define PAD_ 31
__global__ __launch_bounds__(32) void k5_crf(
    const int* __restrict__ mask, const int* __restrict__ gold,
    const float* __restrict__ trans, float* __restrict__ out)
{
    __shared__ unsigned mw[16];
    const int b = blockIdx.x;
    const int k = threadIdx.x;

    float trow[32];
#pragma unroll
    for (int j = 0; j < 32; ++j) trow[j] = trans[k * 32 + j];
    float etr[32];
#pragma unroll
    for (int j = 0; j < 32; ++j) etr[j] = __expf(trow[j]);
    const float trowPAD = trow[PAD_];

    for (int blk = 0; blk < 16; ++blk) {
        int bit = mask[b * T_ + blk * 32 + k];
        unsigned wword = __ballot_sync(0xffffffffu, bit != 0);
        if (k == 0) mw[blk] = wword;
    }
    __syncwarp();

    float score = (k == STOP_) ? 0.f : -10000.f;

    // ---- t = 0: exact per-k LSE ----
    {
        float emit0 = g_htag[((size_t)0 * B_ + b) * 32 + k];
        float v[32];
#pragma unroll
        for (int j = 0; j < 32; ++j)
            v[j] = __shfl_sync(0xffffffffu, score, j) + trow[j];
        float mx = v[0];
#pragma unroll
        for (int j = 1; j < 32; ++j) mx = fmaxf(mx, v[j]);
        float sum = 0.f;
#pragma unroll
        for (int j = 0; j < 32; ++j) sum += __expf(v[j] - mx);
        score = emit0 + mx + __logf(sum);
    }

    float emit = g_htag[((size_t)1 * B_ + b) * 32 + k];

    for (int t = 1; t < T_; ++t) {
        int tn = (t + 1 < T_) ? t + 1 : t;
        float emit_n = g_htag[((size_t)tn * B_ + b) * 32 + k];
        int m = (mw[t >> 5] >> (t & 31)) & 1;

        // group-2 max over j != PAD
        float sEx = (k == PAD_) ? -3.4e38f : score;
#pragma unroll
        for (int o = 16; o; o >>= 1) sEx = fmaxf(sEx, __shfl_xor_sync(0xffffffffu, sEx, o));
        const float M2 = sEx;
        float p = (k == PAD_) ? 0.f : __expf(score - M2);
        float scPAD = __shfl_sync(0xffffffffu, score, PAD_);

        float S = 0.f;
#pragma unroll
        for (int j = 0; j < 32; ++j)
            S = fmaf(__shfl_sync(0xffffffffu, p, j), etr[j], S);

        float Bv = M2 + __logf(S);          // -inf when S==0 (START row)
        float Av = scPAD + trowPAD;          // PAD inflow (exact)
        float mx = fmaxf(Av, Bv);
        float sum = __expf(Av - mx) + __expf(Bv - mx);
        float sn = emit + mx + __logf(sum);
        score = m ? sn : score;
        emit = emit_n;
    }

    float zt = score + trans[STOP_ * 32 + k];
    float mx = zt;
#pragma unroll
    for (int o = 16; o; o >>= 1) mx = fmaxf(mx, __shfl_xor_sync(0xffffffffu, mx, o));
    float es = __expf(zt - mx);
#pragma unroll
    for (int o = 16; o; o >>= 1) es += __shfl_xor_sync(0xffffffffu, es, o);
    float Z = mx + __logf(es);

    float gs = 0.f;
    int len = 0;
    for (int i = k; i < T_; i += 32) {
        int m = mask[b * T_ + i];
        len += m;
        if (i < T_ - 1 && m) {
            int g1 = gold[b * T_ + i + 1];
            int g0 = gold[b * T_ + i];
            gs += g_htag[((size_t)i * B_ + b) * 32 + g1] + trans[g1 * 32 + g0];
        }
    }
#pragma unroll
    for (int o = 16; o; o >>= 1) {
        gs  += __shfl_xor_sync(0xffffffffu, gs, o);
        len += __shfl_xor_sync(0xffffffffu, len, o);
    }
    if (k == 0) {
        int last = gold[b * T_ + len - 1];
        out[b] = Z - (gs + trans[STOP_ * 32 + last]);
    }
}

// =========================================================================
extern "C" void kernel_launch(void* const* d_in, const int* in_sizes, int n_in,
                              void* d_out, int out_size)
{
    const int*   inp   = (const int*)  d_in[0];
    const int*   gold  = (const int*)  d_in[1];
    const int*   mask  = (const int*)  d_in[2];
    const float* emb   = (const float*)d_in[3];
    const float* Wih_f = (const float*)d_in[4];
    const float* Whh_f = (const float*)d_in[5];
    const float* b_f   = (const float*)d_in[6];
    const float* Wih_b = (const float*)d_in[7];
    const float* Whh_b = (const float*)d_in[8];
    const float* b_b   = (const float*)d_in[9];
    const float* W_tag = (const float*)d_in[10];
    const float* b_tag = (const float*)d_in[11];
    const float* trans = (const float*)d_in[12];
    float* out = (float*)d_out;
    (void)in_sizes; (void)n_in; (void)out_size;

    cudaFuncSetAttribute(k1_mma,  cudaFuncAttributeMaxDynamicSharedMemorySize, K1_SMEM);
    cudaFuncSetAttribute(k2_lstm, cudaFuncAttributeMaxDynamicSharedMemorySize, K2_SMEM);

    k0_conv<<<8704, 256>>>(inp, emb, Wih_f, Wih_b);
    k3_wt<<<1, 512>>>(W_tag);
    k1_mma<<<dim3(16, 256), 256, K1_SMEM>>>(b_f, b_b);
    k2_lstm<<<128, 256, K2_SMEM>>>(Whh_f, Whh_b, mask);
    k4_htag<<<(T_ * B_) / 8, 256>>>(b_tag);
    k5_crf<<<B_, 32>>>(mask, gold, trans, out);
}